// round 17
// baseline (speedup 1.0000x reference)
#include <cuda_runtime.h>
#include <cuda_bf16.h>
#include <cstdint>

// ---------------------------------------------------------------------------
// NeuralODE Tsit5 — v17 = v16 (mma.sync bf16x3 emulated-fp32) with SPLIT
// ACCUMULATOR CHAINS: each of the 3 passes (hiA*hiB, hiA*loB, loA*hiB) gets
// its own f32 accumulator quad, giving 6 independent HMMA dependency chains
// per warp (2-tile layers) instead of 2. Summed at the epilogue. Everything
// else (fragment layouts, fused RK, 3 barriers/stage) identical to v16.
// ---------------------------------------------------------------------------

#define NTHREADS 256
#define M_TILE   16

__constant__ float d_cs[6] = {0.0f, 0.161f, 0.327f, 0.9f, 0.9800255409045097f, 1.0f};
__constant__ float d_A[6][5] = {
    {0.f, 0.f, 0.f, 0.f, 0.f},
    {0.161f, 0.f, 0.f, 0.f, 0.f},
    {-0.008480655492356989f, 0.335480655492357f, 0.f, 0.f, 0.f},
    {2.8971530571054935f, -6.359448489975075f, 4.3622954328695815f, 0.f, 0.f},
    {5.325864828439257f, -11.748883564062828f, 7.4955393428898365f, -0.09249506636175525f, 0.f},
    {5.86145544294642f, -12.92096931784711f, 8.159367898576159f, -0.071584973281401f, -0.028269050394068383f}
};
__constant__ float d_B[6] = {
    0.09646076681806523f, 0.01f, 0.4798896504144996f,
    1.379008574103742f, -3.290069515436081f, 2.324710524099774f
};

// ---- helpers ----------------------------------------------------------------
__device__ __forceinline__ uint32_t pk2(float x, float y) {
    __nv_bfloat162 h = __floats2bfloat162_rn(x, y);   // .x = low half
    return *reinterpret_cast<uint32_t*>(&h);
}
__device__ __forceinline__ float bflo(float v) {
    return v - __bfloat162float(__float2bfloat16(v));
}
__device__ __forceinline__ void mma16816(float& d0, float& d1, float& d2, float& d3,
                                         uint32_t a0, uint32_t a1, uint32_t a2, uint32_t a3,
                                         uint32_t b0, uint32_t b1) {
    asm volatile("mma.sync.aligned.m16n8k16.row.col.f32.bf16.bf16.f32 "
        "{%0,%1,%2,%3}, {%4,%5,%6,%7}, {%8,%9}, {%0,%1,%2,%3};"
        : "+f"(d0), "+f"(d1), "+f"(d2), "+f"(d3)
        : "r"(a0), "r"(a1), "r"(a2), "r"(a3), "r"(b0), "r"(b1));
}

// ---- SMEM byte offsets -------------------------------------------------------
#define O_WF0 0              /* [16][4][32] uint4 = 32768 B */
#define O_WF1 32768          /* [16][8][32] uint4 = 65536 B */
#define O_WF2 98304          /* [8][8][32]  uint4 = 32768 B */
#define O_A0H 131072         /* [4][32][4] u32 = 2048 B */
#define O_A0L 133120
#define O_A1H 135168         /* [8][32][4] u32 = 4096 B */
#define O_A1L 139264
#define O_A2H 143360
#define O_A2L 147456
#define O_KB  151552         /* f32 [6][16][68] */
#define O_Y   177664         /* f32 [16][64] */
#define SMEM_BYTES 181760
#define SKB 68
#define KBSTG (16*SKB)

// ---- 2-tile GEMM slice with 6 independent accumulator chains ----------------
template<int KS>
__device__ __forceinline__ void gemm2(const uint4* __restrict__ aH,
                                      const uint4* __restrict__ aL,
                                      const uint4* __restrict__ wfA,
                                      const uint4* __restrict__ wfB,
                                      int lane, float* dA, float* dB) {
    float hA[4] = {0,0,0,0}, mA[4] = {0,0,0,0}, lA[4] = {0,0,0,0};
    float hB[4] = {0,0,0,0}, mB[4] = {0,0,0,0}, lB[4] = {0,0,0,0};
#pragma unroll
    for (int kk = 0; kk < KS; kk++) {
        uint4 ah = aH[kk * 32 + lane];
        uint4 al = aL[kk * 32 + lane];
        uint4 wa = wfA[kk * 32 + lane];
        uint4 wb = wfB[kk * 32 + lane];
        mma16816(hA[0], hA[1], hA[2], hA[3], ah.x, ah.y, ah.z, ah.w, wa.x, wa.y);
        mma16816(mA[0], mA[1], mA[2], mA[3], ah.x, ah.y, ah.z, ah.w, wa.z, wa.w);
        mma16816(lA[0], lA[1], lA[2], lA[3], al.x, al.y, al.z, al.w, wa.x, wa.y);
        mma16816(hB[0], hB[1], hB[2], hB[3], ah.x, ah.y, ah.z, ah.w, wb.x, wb.y);
        mma16816(mB[0], mB[1], mB[2], mB[3], ah.x, ah.y, ah.z, ah.w, wb.z, wb.w);
        mma16816(lB[0], lB[1], lB[2], lB[3], al.x, al.y, al.z, al.w, wb.x, wb.y);
    }
#pragma unroll
    for (int i = 0; i < 4; i++) {
        dA[i] = hA[i] + (mA[i] + lA[i]);
        dB[i] = hB[i] + (mB[i] + lB[i]);
    }
}
// single-tile version (layer 2), 3 chains
template<int KS>
__device__ __forceinline__ void gemm1(const uint4* __restrict__ aH,
                                      const uint4* __restrict__ aL,
                                      const uint4* __restrict__ wf,
                                      int lane, float* d) {
    float h[4] = {0,0,0,0}, m[4] = {0,0,0,0}, l[4] = {0,0,0,0};
#pragma unroll
    for (int kk = 0; kk < KS; kk++) {
        uint4 ah = aH[kk * 32 + lane];
        uint4 al = aL[kk * 32 + lane];
        uint4 wv = wf[kk * 32 + lane];
        mma16816(h[0], h[1], h[2], h[3], ah.x, ah.y, ah.z, ah.w, wv.x, wv.y);
        mma16816(m[0], m[1], m[2], m[3], ah.x, ah.y, ah.z, ah.w, wv.z, wv.w);
        mma16816(l[0], l[1], l[2], l[3], al.x, al.y, al.z, al.w, wv.x, wv.y);
    }
#pragma unroll
    for (int i = 0; i < 4; i++) d[i] = h[i] + (m[i] + l[i]);
}

// epilogue store into next layer's A-fragment slot
__device__ __forceinline__ void epi_store(float v00, float v01, float v10, float v11,
                                          uint32_t* dH, uint32_t* dL, int idx) {
    *reinterpret_cast<uint2*>(dH + idx) = make_uint2(pk2(v00, v01), pk2(v10, v11));
    *reinterpret_cast<uint2*>(dL + idx) =
        make_uint2(pk2(bflo(v00), bflo(v01)), pk2(bflo(v10), bflo(v11)));
}

// ---------------------------------------------------------------------------
__global__ void __launch_bounds__(NTHREADS, 1)
node_kernel(const float* __restrict__ y0, const float* __restrict__ ts,
            const float* __restrict__ w0, const float* __restrict__ b0,
            const float* __restrict__ w1, const float* __restrict__ b1,
            const float* __restrict__ w2, const float* __restrict__ b2,
            float* __restrict__ out, int T) {
    extern __shared__ char smem[];
    uint4* wf0 = (uint4*)(smem + O_WF0);
    uint4* wf1 = (uint4*)(smem + O_WF1);
    uint4* wf2 = (uint4*)(smem + O_WF2);
    uint32_t* a0H = (uint32_t*)(smem + O_A0H);
    uint32_t* a0L = (uint32_t*)(smem + O_A0L);
    uint32_t* a1H = (uint32_t*)(smem + O_A1H);
    uint32_t* a1L = (uint32_t*)(smem + O_A1L);
    uint32_t* a2H = (uint32_t*)(smem + O_A2H);
    uint32_t* a2L = (uint32_t*)(smem + O_A2L);
    float* kbuf = (float*)(smem + O_KB);
    float* ysh  = (float*)(smem + O_Y);

    const int tid  = threadIdx.x;
    const int lane = tid & 31;
    const int warp = tid >> 5;               // 0..7
    const int g    = lane >> 2;              // fragment row group
    const int t2   = (lane & 3) * 2;         // fragment col pair base
    const int row0 = blockIdx.x * M_TILE;

    // ---- setup: weight fragments (hi/lo bf16, mma layout) --------------------
    for (int idx = tid; idx < 16 * 4 * 32; idx += NTHREADS) {      // L0, K=64
        int Tt = idx >> 7, kk = (idx >> 5) & 3, l = idx & 31;
        const float* wr = w0 + (8 * Tt + (l >> 2)) * 65 + 1 + 16 * kk + 2 * (l & 3);
        float v0 = wr[0], v1 = wr[1], v8 = wr[8], v9 = wr[9];
        wf0[idx] = make_uint4(pk2(v0, v1), pk2(v8, v9),
                              pk2(bflo(v0), bflo(v1)), pk2(bflo(v8), bflo(v9)));
    }
    for (int idx = tid; idx < 16 * 8 * 32; idx += NTHREADS) {      // L1, K=128
        int Tt = idx >> 8, kk = (idx >> 5) & 7, l = idx & 31;
        const float* wr = w1 + (8 * Tt + (l >> 2)) * 128 + 16 * kk + 2 * (l & 3);
        float v0 = wr[0], v1 = wr[1], v8 = wr[8], v9 = wr[9];
        wf1[idx] = make_uint4(pk2(v0, v1), pk2(v8, v9),
                              pk2(bflo(v0), bflo(v1)), pk2(bflo(v8), bflo(v9)));
    }
    for (int idx = tid; idx < 8 * 8 * 32; idx += NTHREADS) {       // L2, K=128
        int Tt = idx >> 8, kk = (idx >> 5) & 7, l = idx & 31;
        const float* wr = w2 + (8 * Tt + (l >> 2)) * 128 + 16 * kk + 2 * (l & 3);
        float v0 = wr[0], v1 = wr[1], v8 = wr[8], v9 = wr[9];
        wf2[idx] = make_uint4(pk2(v0, v1), pk2(v8, v9),
                              pk2(bflo(v0), bflo(v1)), pk2(bflo(v8), bflo(v9)));
    }
    // y0 -> ysh + initial act0 fragments
    for (int pi = tid; pi < 512; pi += NTHREADS) {
        int r = pi >> 5, p = pi & 31;
        float v0 = y0[(row0 + r) * 64 + 2 * p];
        float v1 = y0[(row0 + r) * 64 + 2 * p + 1];
        ysh[r * 64 + 2 * p] = v0; ysh[r * 64 + 2 * p + 1] = v1;
        int kstep = p >> 3, pw = p & 7;
        int lp = ((r & 7) << 2) | (pw & 3);
        int j = ((pw >> 2) << 1) | (r >> 3);
        int idx = kstep * 128 + lp * 4 + j;
        a0H[idx] = pk2(v0, v1);
        a0L[idx] = pk2(bflo(v0), bflo(v1));
    }

    // ---- hoisted per-lane bias constants -------------------------------------
    const int cA = 8 * warp + t2;
    const int cB = cA + 64;
    const float b0A0 = b0[cA], b0A1 = b0[cA + 1], b0B0 = b0[cB], b0B1 = b0[cB + 1];
    const float wcA0 = w0[cA * 65], wcA1 = w0[(cA + 1) * 65];
    const float wcB0 = w0[cB * 65], wcB1 = w0[(cB + 1) * 65];
    const float b1A0 = b1[cA], b1A1 = b1[cA + 1], b1B0 = b1[cB], b1B1 = b1[cB + 1];
    const float b2A  = b2[cA], b2B = b2[cA + 1];

    __syncthreads();

    const float dt = ts[1] - ts[0];
    const int steps = T - 1;

    const uint4* a0Hv = (const uint4*)a0H; const uint4* a0Lv = (const uint4*)a0L;
    const uint4* a1Hv = (const uint4*)a1H; const uint4* a1Lv = (const uint4*)a1L;
    const uint4* a2Hv = (const uint4*)a2H; const uint4* a2Lv = (const uint4*)a2L;
    const uint4* wf0A = wf0 + warp * 4 * 32;
    const uint4* wf0B = wf0 + (warp + 8) * 4 * 32;
    const uint4* wf1A = wf1 + warp * 8 * 32;
    const uint4* wf1B = wf1 + (warp + 8) * 8 * 32;
    const uint4* wf2W = wf2 + warp * 8 * 32;

    const int idxA = (warp >> 1) * 128 + lane * 4 + 2 * (warp & 1);  // tile warp
    const int idxB = idxA + 4 * 128;                                 // tile warp+8

    for (int st = 0; st < steps; st++) {
        const float t = ts[st];
        for (int s = 0; s < 6; s++) {
            const float tt = fmaf(d_cs[s], dt, t);

            // ================= Layer 0 =================
            {
                float dA[4], dB4[4];
                gemm2<4>(a0Hv, a0Lv, wf0A, wf0B, lane, dA, dB4);
                const float vA0 = fmaf(wcA0, tt, b0A0), vA1 = fmaf(wcA1, tt, b0A1);
                const float vB0 = fmaf(wcB0, tt, b0B0), vB1 = fmaf(wcB1, tt, b0B1);
                epi_store(fmaxf(dA[0] + vA0, 0.f), fmaxf(dA[1] + vA1, 0.f),
                          fmaxf(dA[2] + vA0, 0.f), fmaxf(dA[3] + vA1, 0.f),
                          a1H, a1L, idxA);
                epi_store(fmaxf(dB4[0] + vB0, 0.f), fmaxf(dB4[1] + vB1, 0.f),
                          fmaxf(dB4[2] + vB0, 0.f), fmaxf(dB4[3] + vB1, 0.f),
                          a1H, a1L, idxB);
            }
            __syncthreads();

            // ================= Layer 1 =================
            {
                float dA[4], dB4[4];
                gemm2<8>(a1Hv, a1Lv, wf1A, wf1B, lane, dA, dB4);
                epi_store(fmaxf(dA[0] + b1A0, 0.f), fmaxf(dA[1] + b1A1, 0.f),
                          fmaxf(dA[2] + b1A0, 0.f), fmaxf(dA[3] + b1A1, 0.f),
                          a2H, a2L, idxA);
                epi_store(fmaxf(dB4[0] + b1B0, 0.f), fmaxf(dB4[1] + b1B1, 0.f),
                          fmaxf(dB4[2] + b1B0, 0.f), fmaxf(dB4[3] + b1B1, 0.f),
                          a2H, a2L, idxB);
            }
            __syncthreads();

            // ================= Layer 2 + fused RK ======
            {
                float d[4];
                gemm1<8>(a2Hv, a2Lv, wf2W, lane, d);
                const float k00 = d[0] + b2A, k01 = d[1] + b2B;
                const float k10 = d[2] + b2A, k11 = d[3] + b2B;

                const float y00 = ysh[g * 64 + cA],       y01 = ysh[g * 64 + cA + 1];
                const float y10 = ysh[(g + 8) * 64 + cA], y11 = ysh[(g + 8) * 64 + cA + 1];
                float v00, v01, v10, v11;

                if (s < 5) {
                    *(float2*)(kbuf + s * KBSTG + g * SKB + cA) = make_float2(k00, k01);
                    *(float2*)(kbuf + s * KBSTG + (g + 8) * SKB + cA) = make_float2(k10, k11);
                    const float cs = d_A[s + 1][s];
                    float a00 = cs * k00, a01 = cs * k01, a10 = cs * k10, a11 = cs * k11;
                    for (int j = 0; j < s; j++) {
                        const float cj = d_A[s + 1][j];
                        float2 p0 = *(const float2*)(kbuf + j * KBSTG + g * SKB + cA);
                        float2 p1 = *(const float2*)(kbuf + j * KBSTG + (g + 8) * SKB + cA);
                        a00 = fmaf(cj, p0.x, a00); a01 = fmaf(cj, p0.y, a01);
                        a10 = fmaf(cj, p1.x, a10); a11 = fmaf(cj, p1.y, a11);
                    }
                    v00 = fmaf(dt, a00, y00); v01 = fmaf(dt, a01, y01);
                    v10 = fmaf(dt, a10, y10); v11 = fmaf(dt, a11, y11);
                } else {
                    const float c5 = d_B[5];
                    float a00 = c5 * k00, a01 = c5 * k01, a10 = c5 * k10, a11 = c5 * k11;
#pragma unroll
                    for (int j = 0; j < 5; j++) {
                        const float cj = d_B[j];
                        float2 p0 = *(const float2*)(kbuf + j * KBSTG + g * SKB + cA);
                        float2 p1 = *(const float2*)(kbuf + j * KBSTG + (g + 8) * SKB + cA);
                        a00 = fmaf(cj, p0.x, a00); a01 = fmaf(cj, p0.y, a01);
                        a10 = fmaf(cj, p1.x, a10); a11 = fmaf(cj, p1.y, a11);
                    }
                    v00 = fmaf(dt, a00, y00); v01 = fmaf(dt, a01, y01);
                    v10 = fmaf(dt, a10, y10); v11 = fmaf(dt, a11, y11);
                    *(float2*)(ysh + g * 64 + cA)       = make_float2(v00, v01);
                    *(float2*)(ysh + (g + 8) * 64 + cA) = make_float2(v10, v11);
                    if (st == steps - 1) {
                        *(float2*)(out + (row0 + g) * 64 + cA)     = make_float2(v00, v01);
                        *(float2*)(out + (row0 + g + 8) * 64 + cA) = make_float2(v10, v11);
                    }
                }
                epi_store(v00, v01, v10, v11, a0H, a0L, idxA);
            }
            __syncthreads();
        }
    }
}

// ---------------------------------------------------------------------------
extern "C" void kernel_launch(void* const* d_in, const int* in_sizes, int n_in,
                              void* d_out, int out_size) {
    const float* y0 = (const float*)d_in[0];
    const float* ts = (const float*)d_in[1];
    const float* w0 = (const float*)d_in[2];
    const float* b0 = (const float*)d_in[3];
    const float* w1 = (const float*)d_in[4];
    const float* b1 = (const float*)d_in[5];
    const float* w2 = (const float*)d_in[6];
    const float* b2 = (const float*)d_in[7];

    const int B = in_sizes[0] / 64;
    const int T = in_sizes[1];

    cudaFuncSetAttribute(node_kernel,
                         cudaFuncAttributeMaxDynamicSharedMemorySize, SMEM_BYTES);

    node_kernel<<<B / M_TILE, NTHREADS, SMEM_BYTES>>>(
        y0, ts, w0, b0, w1, b1, w2, b2, (float*)d_out, T);
}